// round 11
// baseline (speedup 1.0000x reference)
#include <cuda_runtime.h>
#include <cuda_fp16.h>
#include <cstdint>
#include <math.h>

// Problem constants
#define B_SZ 2
#define L_SZ 2048
#define D_SZ 1024
#define N_SZ 16
#define M_TOT (B_SZ * L_SZ)      // 4096
#define K_DIM D_SZ               // 1024
#define NOUT_BC (D_SZ * N_SZ)    // 16384

#define NC 8                     // scan chunks
#define CL (L_SZ / NC)           // 256

// Scratch (device globals: allocation-free rule)
__device__ __half g_dt[M_TOT * D_SZ];                       // 8 MB
__device__ __half g_Bt[(size_t)M_TOT * NOUT_BC];            // 128 MB
__device__ __half g_Ct[(size_t)M_TOT * NOUT_BC];            // 128 MB
// fp16 copies of U and weights
__device__ __half g_Uh[M_TOT * K_DIM];                      // 8 MB
__device__ __half g_Wdth[D_SZ * K_DIM];                     // 2 MB
__device__ __half g_WBh[(size_t)NOUT_BC * K_DIM];           // 32 MB
__device__ __half g_WCh[(size_t)NOUT_BC * K_DIM];           // 32 MB
// scan chunk state
__device__ float g_P[B_SZ * D_SZ * NC * N_SZ];
__device__ float g_H[B_SZ * D_SZ * NC * N_SZ];
__device__ float g_hs[B_SZ * D_SZ * NC * N_SZ];

// ---------------------------------------------------------------------------
// helpers
// ---------------------------------------------------------------------------
__device__ __forceinline__ uint32_t smem_u32(const void* p) {
    uint32_t a;
    asm("{ .reg .u64 t; cvta.to.shared.u64 t, %1; cvt.u32.u64 %0, t; }"
        : "=r"(a) : "l"(p));
    return a;
}
__device__ __forceinline__ void cp_async16(uint32_t dst, const void* src) {
    asm volatile("cp.async.cg.shared.global [%0], [%1], 16;"
                 :: "r"(dst), "l"(src) : "memory");
}
__device__ __forceinline__ float softplus_f(float x) {
    return (x > 20.0f) ? x : log1pf(expf(x));
}
__device__ __forceinline__ void mma_f16(float* c, const uint32_t* a,
                                        const uint32_t* b) {
    asm volatile(
        "mma.sync.aligned.m16n8k16.row.col.f32.f16.f16.f32 "
        "{%0,%1,%2,%3}, {%4,%5,%6,%7}, {%8,%9}, {%0,%1,%2,%3};"
        : "+f"(c[0]), "+f"(c[1]), "+f"(c[2]), "+f"(c[3])
        : "r"(a[0]), "r"(a[1]), "r"(a[2]), "r"(a[3]), "r"(b[0]), "r"(b[1]));
}
__device__ __forceinline__ void ldsm_x4(uint32_t* r, uint32_t addr) {
    asm volatile("ldmatrix.sync.aligned.m8n8.x4.shared.b16 {%0,%1,%2,%3}, [%4];"
                 : "=r"(r[0]), "=r"(r[1]), "=r"(r[2]), "=r"(r[3]) : "r"(addr));
}

// ---------------------------------------------------------------------------
// fp32 -> fp16 (rne) conversion pre-pass (memory-bound, 2 float4 per thread)
// ---------------------------------------------------------------------------
__global__ __launch_bounds__(256)
void f2h_kernel(const float* __restrict__ in, __half* __restrict__ out, int n4) {
    int i = (blockIdx.x * blockDim.x + threadIdx.x) * 2;
    if (i + 1 < n4) {
        float4 v0 = ((const float4*)in)[i];
        float4 v1 = ((const float4*)in)[i + 1];
        ((__half2*)out)[2 * i]     = __floats2half2_rn(v0.x, v0.y);
        ((__half2*)out)[2 * i + 1] = __floats2half2_rn(v0.z, v0.w);
        ((__half2*)out)[2 * i + 2] = __floats2half2_rn(v1.x, v1.y);
        ((__half2*)out)[2 * i + 3] = __floats2half2_rn(v1.z, v1.w);
    } else if (i < n4) {
        float4 v0 = ((const float4*)in)[i];
        ((__half2*)out)[2 * i]     = __floats2half2_rn(v0.x, v0.y);
        ((__half2*)out)[2 * i + 1] = __floats2half2_rn(v0.z, v0.w);
    }
}

// ---------------------------------------------------------------------------
// GEMM (mma.sync fp16 m16n8k16 + ldmatrix + 3-stage cp.async pipeline)
//   mode 0: half out, softplus(val + bias + bias2)   (dt path)
//   mode 1: half out, val + bias                     (B/C path)
// part < 0 : by = blockIdx.y (full grid)
// part >= 0: grid.y == 16; by = (y>>3)*16 + part*8 + (y&7)
//            (part covers l in [part*1024, (part+1)*1024) for both batches;
//             2 partitions of 2048 CTAs = 7+7 wave-slots == 14 of full launch)
// ---------------------------------------------------------------------------
#define HSTRIDE 72               // halves per row (64 + 8 pad); 144B rows
#define TILE_B (128 * HSTRIDE * 2)       // bytes per tile = 18432
#define NSTAGE 3
#define GEMM_SMEM (NSTAGE * 2 * TILE_B)  // 110592 bytes

__global__ __launch_bounds__(128, 2)
void gemm_mma_h(const __half* __restrict__ U, const __half* __restrict__ W,
                const float* __restrict__ bias, const float* __restrict__ bias2,
                __half* __restrict__ out, int Nout, int mode, int part)
{
    extern __shared__ char smc[];
    const int tid = threadIdx.x;
    const int wid = tid >> 5;
    const int lane = tid & 31;
    const int bx = blockIdx.x;      // N tile
    int by;
    if (part < 0) by = blockIdx.y;
    else by = (blockIdx.y >> 3) * 16 + part * 8 + (blockIdx.y & 7);
    const int m0 = (wid & 1) * 64, n0 = (wid >> 1) * 64;
    const int g = lane >> 2, t4 = lane & 3;

    const __half* Ag = U + (size_t)(by * 128) * K_DIM;
    const __half* Bg = W + (size_t)(bx * 128) * K_DIM;

    const int sel = lane >> 3;
    const int lr  = lane & 7;
    uint32_t aoff[4];
#pragma unroll
    for (int mt = 0; mt < 4; ++mt) {
        int row = m0 + mt * 16 + lr + (sel & 1) * 8;
        int kh  = (sel >> 1) * 8;
        aoff[mt] = (uint32_t)((row * HSTRIDE + kh) * 2);
    }
    uint32_t boff[4];
#pragma unroll
    for (int ntp = 0; ntp < 4; ++ntp) {
        int row = n0 + (2 * ntp + (sel >> 1)) * 8 + lr;
        int kh  = (sel & 1) * 8;
        boff[ntp] = (uint32_t)((row * HSTRIDE + kh) * 2);
    }

    float acc[4][8][4];
#pragma unroll
    for (int mt = 0; mt < 4; ++mt)
#pragma unroll
        for (int nt = 0; nt < 8; ++nt)
#pragma unroll
            for (int j = 0; j < 4; ++j) acc[mt][nt][j] = 0.0f;

    const int NK = K_DIM / 64;      // 16 k-tiles
    const uint32_t sm_u = smem_u32(smc);

    auto issue = [&](int it, int stg) {
        char* As = smc + stg * 2 * TILE_B;
        char* Bs = As + TILE_B;
        const int kc = it * 64;
#pragma unroll
        for (int i = 0; i < 8; ++i) {
            int id = tid + i * 128;
            int row = id >> 3;
            int q = id & 7;
            cp_async16(smem_u32(As + (row * HSTRIDE + q * 8) * 2),
                       Ag + (size_t)row * K_DIM + kc + q * 8);
            cp_async16(smem_u32(Bs + (row * HSTRIDE + q * 8) * 2),
                       Bg + (size_t)row * K_DIM + kc + q * 8);
        }
        asm volatile("cp.async.commit_group;" ::: "memory");
    };

    issue(0, 0);
    issue(1, 1);
    for (int it = 0; it < NK; ++it) {
        if (it < NK - 1) {
            asm volatile("cp.async.wait_group 1;" ::: "memory");
        } else {
            asm volatile("cp.async.wait_group 0;" ::: "memory");
        }
        __syncthreads();
        if (it + 2 < NK) issue(it + 2, (it + 2) % NSTAGE);

        const uint32_t As_u = sm_u + (uint32_t)((it % NSTAGE) * 2 * TILE_B);
        const uint32_t Bs_u = As_u + (uint32_t)TILE_B;
#pragma unroll
        for (int ks = 0; ks < 4; ++ks) {
            const uint32_t kb = ks * 32;
            uint32_t a[4][4], b[4][4];
#pragma unroll
            for (int mt = 0; mt < 4; ++mt)
                ldsm_x4(a[mt], As_u + aoff[mt] + kb);
#pragma unroll
            for (int ntp = 0; ntp < 4; ++ntp)
                ldsm_x4(b[ntp], Bs_u + boff[ntp] + kb);
#pragma unroll
            for (int mt = 0; mt < 4; ++mt)
#pragma unroll
                for (int nt = 0; nt < 8; ++nt)
                    mma_f16(acc[mt][nt], a[mt], &b[nt >> 1][(nt & 1) * 2]);
        }
    }

    // Epilogue (half output, bias / softplus fused)
#pragma unroll
    for (int nt = 0; nt < 8; ++nt) {
        const int col = bx * 128 + n0 + nt * 8 + t4 * 2;
        float b0 = bias[col], b1 = bias[col + 1];
        float e0 = 0.f, e1 = 0.f;
        if (mode == 0) { e0 = bias2[col]; e1 = bias2[col + 1]; }
#pragma unroll
        for (int mt = 0; mt < 4; ++mt) {
            const int row = by * 128 + m0 + mt * 16 + g;
            float v0 = acc[mt][nt][0] + b0;
            float v1 = acc[mt][nt][1] + b1;
            float v2 = acc[mt][nt][2] + b0;
            float v3 = acc[mt][nt][3] + b1;
            if (mode == 0) {
                v0 = softplus_f(v0 + e0); v1 = softplus_f(v1 + e1);
                v2 = softplus_f(v2 + e0); v3 = softplus_f(v3 + e1);
            }
            *(__half2*)&out[(size_t)row * Nout + col] = __floats2half2_rn(v0, v1);
            *(__half2*)&out[(size_t)(row + 8) * Nout + col] =
                __floats2half2_rn(v2, v3);
        }
    }
}

// ---------------------------------------------------------------------------
// Chunked scan. dt/Bt/Ct fp16; state math fp32.
// ---------------------------------------------------------------------------
__global__ __launch_bounds__(256)
void scan_pass1(const float* __restrict__ u, const float* __restrict__ log_A,
                const __half* __restrict__ dt, const __half* __restrict__ Bt,
                float* __restrict__ P, float* __restrict__ H)
{
    const int tid = threadIdx.x;
    const int lane = tid & 31;
    const int half = lane >> 4;
    const int n = lane & 15;
    const int warp = tid >> 5;
    const int p = blockIdx.x * 16 + warp * 2 + half;
    const int c = blockIdx.y;
    const int b = p >> 10;
    const int d = p & 1023;

    const float A = -expf(log_A[d * N_SZ + n]);
    const float invA = 1.0f / A;

    size_t base = (size_t)b * L_SZ * D_SZ + (size_t)c * CL * D_SZ + d;
    const __half* dtp = dt + base;
    const float* up  = u + base;
    const __half* bp = Bt + base * N_SZ + n;

    float h = 0.0f, aprod = 1.0f;
#pragma unroll 4
    for (int t = 0; t < CL; ++t) {
        float a = __expf(__half2float(*dtp) * A);
        float x = (a - 1.0f) * invA * __half2float(*bp) * (*up);
        h = fmaf(a, h, x);
        aprod *= a;
        dtp += D_SZ; up += D_SZ; bp += (size_t)D_SZ * N_SZ;
    }
    const int idx = (p * NC + c) * N_SZ + n;
    P[idx] = aprod;
    H[idx] = h;
}

__global__ __launch_bounds__(256)
void scan_chain(const float* __restrict__ P, const float* __restrict__ H,
                float* __restrict__ hs)
{
    const int id = blockIdx.x * blockDim.x + threadIdx.x;
    const int p = id >> 4;
    const int n = id & 15;
    float h = 0.0f;
#pragma unroll
    for (int c = 0; c < NC; ++c) {
        const int idx = (p * NC + c) * N_SZ + n;
        hs[idx] = h;
        h = fmaf(P[idx], h, H[idx]);
    }
}

__global__ __launch_bounds__(256)
void scan_pass2(const float* __restrict__ u, const float* __restrict__ log_A,
                const float* __restrict__ D_skip,
                const __half* __restrict__ dt, const __half* __restrict__ Bt,
                const __half* __restrict__ Ct, const float* __restrict__ hs,
                float* __restrict__ out, int c0)
{
    const int tid = threadIdx.x;
    const int lane = tid & 31;
    const int half = lane >> 4;
    const int n = lane & 15;
    const int warp = tid >> 5;
    const int p = blockIdx.x * 16 + warp * 2 + half;
    const int c = c0 + blockIdx.y;
    const int b = p >> 10;
    const int d = p & 1023;

    const float A = -expf(log_A[d * N_SZ + n]);
    const float invA = 1.0f / A;
    const float Dsk = D_skip[d];

    size_t base = (size_t)b * L_SZ * D_SZ + (size_t)c * CL * D_SZ + d;
    const __half* dtp = dt + base;
    const float* up  = u + base;
    float* op        = out + base;
    const __half* bp = Bt + base * N_SZ + n;
    const __half* cp = Ct + base * N_SZ + n;

    float h = hs[(p * NC + c) * N_SZ + n];
#pragma unroll 4
    for (int t = 0; t < CL; ++t) {
        float uv = *up;
        float a = __expf(__half2float(*dtp) * A);
        float x = (a - 1.0f) * invA * __half2float(*bp) * uv;
        h = fmaf(a, h, x);
        float prod = __half2float(*cp) * h;
        prod += __shfl_xor_sync(0xffffffffu, prod, 1);
        prod += __shfl_xor_sync(0xffffffffu, prod, 2);
        prod += __shfl_xor_sync(0xffffffffu, prod, 4);
        prod += __shfl_xor_sync(0xffffffffu, prod, 8);
        if (n == 0) *op = fmaf(Dsk, uv, prod);
        dtp += D_SZ; up += D_SZ; op += D_SZ;
        bp += (size_t)D_SZ * N_SZ; cp += (size_t)D_SZ * N_SZ;
    }
}

// ---------------------------------------------------------------------------
// Launch: serialized GEMMs; pass1+chain under gemm_C part0; pass2 chunks 0-3
// under gemm_C part1; only pass2 chunks 4-7 exposed.
// s0: f2h_u, f2h_Wdt, gemm_dt, [evWB] gemm_B -> evB,
//     [evWC] gemm_C part0 -> evC0, gemm_C part1 -> evC1
// s1: f2h_WB -> evWB, f2h_WC -> evWC, [evB] pass1 + chain,
//     [evC0] pass2 chunks 0-3, [evC1] pass2 chunks 4-7 -> evDone
// join: s0 waits evDone
// ---------------------------------------------------------------------------
extern "C" void kernel_launch(void* const* d_in, const int* in_sizes, int n_in,
                              void* d_out, int out_size)
{
    const float* u       = (const float*)d_in[0];
    const float* log_A   = (const float*)d_in[1];
    const float* D_skip  = (const float*)d_in[2];
    const float* dt_bias = (const float*)d_in[3];
    const float* W_dt    = (const float*)d_in[4];
    const float* b_dt    = (const float*)d_in[5];
    const float* W_B     = (const float*)d_in[6];
    const float* b_B     = (const float*)d_in[7];
    const float* W_C     = (const float*)d_in[8];
    const float* b_C     = (const float*)d_in[9];
    float* out = (float*)d_out;

    float *P, *H, *hs;
    __half *dt_buf, *B_buf, *C_buf, *Uh, *Wdth, *WBh, *WCh;
    cudaGetSymbolAddress((void**)&dt_buf, g_dt);
    cudaGetSymbolAddress((void**)&B_buf, g_Bt);
    cudaGetSymbolAddress((void**)&C_buf, g_Ct);
    cudaGetSymbolAddress((void**)&Uh, g_Uh);
    cudaGetSymbolAddress((void**)&Wdth, g_Wdth);
    cudaGetSymbolAddress((void**)&WBh, g_WBh);
    cudaGetSymbolAddress((void**)&WCh, g_WCh);
    cudaGetSymbolAddress((void**)&P, g_P);
    cudaGetSymbolAddress((void**)&H, g_H);
    cudaGetSymbolAddress((void**)&hs, g_hs);

    static cudaStream_t s1 = nullptr;
    static cudaEvent_t evRoot = nullptr, evWB = nullptr, evWC = nullptr,
                       evB = nullptr, evC0 = nullptr, evC1 = nullptr,
                       evDone = nullptr;
    if (!s1) {
        cudaStreamCreateWithFlags(&s1, cudaStreamNonBlocking);
        cudaEventCreateWithFlags(&evRoot, cudaEventDisableTiming);
        cudaEventCreateWithFlags(&evWB, cudaEventDisableTiming);
        cudaEventCreateWithFlags(&evWC, cudaEventDisableTiming);
        cudaEventCreateWithFlags(&evB, cudaEventDisableTiming);
        cudaEventCreateWithFlags(&evC0, cudaEventDisableTiming);
        cudaEventCreateWithFlags(&evC1, cudaEventDisableTiming);
        cudaEventCreateWithFlags(&evDone, cudaEventDisableTiming);
        cudaFuncSetAttribute(gemm_mma_h,
                             cudaFuncAttributeMaxDynamicSharedMemorySize,
                             GEMM_SMEM);
    }

    const int n4_big = (int)((size_t)NOUT_BC * K_DIM / 4);

    // fork s1
    cudaEventRecord(evRoot, 0);
    cudaStreamWaitEvent(s1, evRoot, 0);

    // ---- s1: weight converts ----
    f2h_kernel<<<(n4_big / 2 + 255) / 256, 256, 0, s1>>>(W_B, WBh, n4_big);
    cudaEventRecord(evWB, s1);
    f2h_kernel<<<(n4_big / 2 + 255) / 256, 256, 0, s1>>>(W_C, WCh, n4_big);
    cudaEventRecord(evWC, s1);

    // ---- s0: u/Wdt converts, dt GEMM, B GEMM (full), C GEMM (2 halves) ----
    f2h_kernel<<<(M_TOT * K_DIM / 8 + 255) / 256, 256>>>(u, Uh,
                                                         M_TOT * K_DIM / 4);
    f2h_kernel<<<(D_SZ * K_DIM / 8 + 255) / 256, 256>>>(W_dt, Wdth,
                                                        D_SZ * K_DIM / 4);
    gemm_mma_h<<<dim3(D_SZ / 128, M_TOT / 128), 128, GEMM_SMEM>>>(
        Uh, Wdth, b_dt, dt_bias, dt_buf, D_SZ, 0, -1);
    cudaStreamWaitEvent(0, evWB, 0);
    gemm_mma_h<<<dim3(NOUT_BC / 128, M_TOT / 128), 128, GEMM_SMEM>>>(
        Uh, WBh, b_B, nullptr, B_buf, NOUT_BC, 1, -1);
    cudaEventRecord(evB, 0);
    cudaStreamWaitEvent(0, evWC, 0);
    gemm_mma_h<<<dim3(NOUT_BC / 128, 16), 128, GEMM_SMEM>>>(
        Uh, WCh, b_C, nullptr, C_buf, NOUT_BC, 1, 0);
    cudaEventRecord(evC0, 0);
    gemm_mma_h<<<dim3(NOUT_BC / 128, 16), 128, GEMM_SMEM>>>(
        Uh, WCh, b_C, nullptr, C_buf, NOUT_BC, 1, 1);
    cudaEventRecord(evC1, 0);

    // ---- s1: pass1+chain under gemm_C part0; pass2 halves after evC0/evC1 ----
    cudaStreamWaitEvent(s1, evB, 0);
    scan_pass1<<<dim3(B_SZ * D_SZ / 16, NC), 256, 0, s1>>>(u, log_A, dt_buf,
                                                           B_buf, P, H);
    scan_chain<<<B_SZ * D_SZ * N_SZ / 256, 256, 0, s1>>>(P, H, hs);
    cudaStreamWaitEvent(s1, evC0, 0);
    scan_pass2<<<dim3(B_SZ * D_SZ / 16, 4), 256, 0, s1>>>(
        u, log_A, D_skip, dt_buf, B_buf, C_buf, hs, out, 0);
    cudaStreamWaitEvent(s1, evC1, 0);
    scan_pass2<<<dim3(B_SZ * D_SZ / 16, 4), 256, 0, s1>>>(
        u, log_A, D_skip, dt_buf, B_buf, C_buf, hs, out, 4);
    cudaEventRecord(evDone, s1);

    // join
    cudaStreamWaitEvent(0, evDone, 0);
}

// round 12
// speedup vs baseline: 1.0549x; 1.0549x over previous
#include <cuda_runtime.h>
#include <cuda_fp16.h>
#include <cstdint>
#include <math.h>

// Problem constants
#define B_SZ 2
#define L_SZ 2048
#define D_SZ 1024
#define N_SZ 16
#define M_TOT (B_SZ * L_SZ)      // 4096
#define K_DIM D_SZ               // 1024
#define NOUT_BC (D_SZ * N_SZ)    // 16384

#define NC 8                     // scan chunks
#define CL (L_SZ / NC)           // 256

// Scratch (device globals: allocation-free rule)
__device__ __half g_dt[M_TOT * D_SZ];                       // 8 MB
__device__ __half g_Bt[(size_t)M_TOT * NOUT_BC];            // 128 MB
__device__ __half g_Ct[(size_t)M_TOT * NOUT_BC];            // 128 MB
// fp16 copies of U and weights
__device__ __half g_Uh[M_TOT * K_DIM];                      // 8 MB
__device__ __half g_Wdth[D_SZ * K_DIM];                     // 2 MB
__device__ __half g_WBh[(size_t)NOUT_BC * K_DIM];           // 32 MB
__device__ __half g_WCh[(size_t)NOUT_BC * K_DIM];           // 32 MB
// scan chunk state
__device__ float g_P[B_SZ * D_SZ * NC * N_SZ];
__device__ float g_H[B_SZ * D_SZ * NC * N_SZ];
__device__ float g_hs[B_SZ * D_SZ * NC * N_SZ];

// ---------------------------------------------------------------------------
// helpers
// ---------------------------------------------------------------------------
__device__ __forceinline__ uint32_t smem_u32(const void* p) {
    uint32_t a;
    asm("{ .reg .u64 t; cvta.to.shared.u64 t, %1; cvt.u32.u64 %0, t; }"
        : "=r"(a) : "l"(p));
    return a;
}
__device__ __forceinline__ void cp_async16(uint32_t dst, const void* src) {
    asm volatile("cp.async.cg.shared.global [%0], [%1], 16;"
                 :: "r"(dst), "l"(src) : "memory");
}
__device__ __forceinline__ float softplus_f(float x) {
    return (x > 20.0f) ? x : log1pf(expf(x));
}
__device__ __forceinline__ void mma_f16(float* c, const uint32_t* a,
                                        const uint32_t* b) {
    asm volatile(
        "mma.sync.aligned.m16n8k16.row.col.f32.f16.f16.f32 "
        "{%0,%1,%2,%3}, {%4,%5,%6,%7}, {%8,%9}, {%0,%1,%2,%3};"
        : "+f"(c[0]), "+f"(c[1]), "+f"(c[2]), "+f"(c[3])
        : "r"(a[0]), "r"(a[1]), "r"(a[2]), "r"(a[3]), "r"(b[0]), "r"(b[1]));
}
__device__ __forceinline__ void ldsm_x4(uint32_t* r, uint32_t addr) {
    asm volatile("ldmatrix.sync.aligned.m8n8.x4.shared.b16 {%0,%1,%2,%3}, [%4];"
                 : "=r"(r[0]), "=r"(r[1]), "=r"(r[2]), "=r"(r[3]) : "r"(addr));
}

// ---------------------------------------------------------------------------
// fp32 -> fp16 (rne) conversion pre-pass (memory-bound, 2 float4 per thread)
// ---------------------------------------------------------------------------
__global__ __launch_bounds__(256)
void f2h_kernel(const float* __restrict__ in, __half* __restrict__ out, int n4) {
    int i = (blockIdx.x * blockDim.x + threadIdx.x) * 2;
    if (i + 1 < n4) {
        float4 v0 = ((const float4*)in)[i];
        float4 v1 = ((const float4*)in)[i + 1];
        ((__half2*)out)[2 * i]     = __floats2half2_rn(v0.x, v0.y);
        ((__half2*)out)[2 * i + 1] = __floats2half2_rn(v0.z, v0.w);
        ((__half2*)out)[2 * i + 2] = __floats2half2_rn(v1.x, v1.y);
        ((__half2*)out)[2 * i + 3] = __floats2half2_rn(v1.z, v1.w);
    } else if (i < n4) {
        float4 v0 = ((const float4*)in)[i];
        ((__half2*)out)[2 * i]     = __floats2half2_rn(v0.x, v0.y);
        ((__half2*)out)[2 * i + 1] = __floats2half2_rn(v0.z, v0.w);
    }
}

// ---------------------------------------------------------------------------
// GEMM (mma.sync fp16 m16n8k16 + ldmatrix + 3-stage cp.async pipeline)
//   mode 0: half out, softplus(val + bias + bias2)   (dt path)
//   mode 1: half out, val + bias                     (B/C path)
// 128 threads (4 warps), CTA tile 128x128, BK=64, one barrier per k-tile.
// ---------------------------------------------------------------------------
#define HSTRIDE 72               // halves per row (64 + 8 pad); 144B rows
#define TILE_B (128 * HSTRIDE * 2)       // bytes per tile = 18432
#define NSTAGE 3
#define GEMM_SMEM (NSTAGE * 2 * TILE_B)  // 110592 bytes

__global__ __launch_bounds__(128, 2)
void gemm_mma_h(const __half* __restrict__ U, const __half* __restrict__ W,
                const float* __restrict__ bias, const float* __restrict__ bias2,
                __half* __restrict__ out, int Nout, int mode)
{
    extern __shared__ char smc[];
    const int tid = threadIdx.x;
    const int wid = tid >> 5;
    const int lane = tid & 31;
    const int bx = blockIdx.x;      // N tile
    const int by = blockIdx.y;      // M tile
    const int m0 = (wid & 1) * 64, n0 = (wid >> 1) * 64;
    const int g = lane >> 2, t4 = lane & 3;

    const __half* Ag = U + (size_t)(by * 128) * K_DIM;
    const __half* Bg = W + (size_t)(bx * 128) * K_DIM;

    const int sel = lane >> 3;
    const int lr  = lane & 7;
    uint32_t aoff[4];
#pragma unroll
    for (int mt = 0; mt < 4; ++mt) {
        int row = m0 + mt * 16 + lr + (sel & 1) * 8;
        int kh  = (sel >> 1) * 8;
        aoff[mt] = (uint32_t)((row * HSTRIDE + kh) * 2);
    }
    uint32_t boff[4];
#pragma unroll
    for (int ntp = 0; ntp < 4; ++ntp) {
        int row = n0 + (2 * ntp + (sel >> 1)) * 8 + lr;
        int kh  = (sel & 1) * 8;
        boff[ntp] = (uint32_t)((row * HSTRIDE + kh) * 2);
    }

    float acc[4][8][4];
#pragma unroll
    for (int mt = 0; mt < 4; ++mt)
#pragma unroll
        for (int nt = 0; nt < 8; ++nt)
#pragma unroll
            for (int j = 0; j < 4; ++j) acc[mt][nt][j] = 0.0f;

    const int NK = K_DIM / 64;      // 16 k-tiles
    const uint32_t sm_u = smem_u32(smc);

    auto issue = [&](int it, int stg) {
        char* As = smc + stg * 2 * TILE_B;
        char* Bs = As + TILE_B;
        const int kc = it * 64;
#pragma unroll
        for (int i = 0; i < 8; ++i) {
            int id = tid + i * 128;
            int row = id >> 3;
            int q = id & 7;
            cp_async16(smem_u32(As + (row * HSTRIDE + q * 8) * 2),
                       Ag + (size_t)row * K_DIM + kc + q * 8);
            cp_async16(smem_u32(Bs + (row * HSTRIDE + q * 8) * 2),
                       Bg + (size_t)row * K_DIM + kc + q * 8);
        }
        asm volatile("cp.async.commit_group;" ::: "memory");
    };

    issue(0, 0);
    issue(1, 1);
    for (int it = 0; it < NK; ++it) {
        if (it < NK - 1) {
            asm volatile("cp.async.wait_group 1;" ::: "memory");
        } else {
            asm volatile("cp.async.wait_group 0;" ::: "memory");
        }
        __syncthreads();
        if (it + 2 < NK) issue(it + 2, (it + 2) % NSTAGE);

        const uint32_t As_u = sm_u + (uint32_t)((it % NSTAGE) * 2 * TILE_B);
        const uint32_t Bs_u = As_u + (uint32_t)TILE_B;
#pragma unroll
        for (int ks = 0; ks < 4; ++ks) {
            const uint32_t kb = ks * 32;
            uint32_t a[4][4], b[4][4];
#pragma unroll
            for (int mt = 0; mt < 4; ++mt)
                ldsm_x4(a[mt], As_u + aoff[mt] + kb);
#pragma unroll
            for (int ntp = 0; ntp < 4; ++ntp)
                ldsm_x4(b[ntp], Bs_u + boff[ntp] + kb);
#pragma unroll
            for (int mt = 0; mt < 4; ++mt)
#pragma unroll
                for (int nt = 0; nt < 8; ++nt)
                    mma_f16(acc[mt][nt], a[mt], &b[nt >> 1][(nt & 1) * 2]);
        }
    }

    // Epilogue (half output, bias / softplus fused)
#pragma unroll
    for (int nt = 0; nt < 8; ++nt) {
        const int col = bx * 128 + n0 + nt * 8 + t4 * 2;
        float b0 = bias[col], b1 = bias[col + 1];
        float e0 = 0.f, e1 = 0.f;
        if (mode == 0) { e0 = bias2[col]; e1 = bias2[col + 1]; }
#pragma unroll
        for (int mt = 0; mt < 4; ++mt) {
            const int row = by * 128 + m0 + mt * 16 + g;
            float v0 = acc[mt][nt][0] + b0;
            float v1 = acc[mt][nt][1] + b1;
            float v2 = acc[mt][nt][2] + b0;
            float v3 = acc[mt][nt][3] + b1;
            if (mode == 0) {
                v0 = softplus_f(v0 + e0); v1 = softplus_f(v1 + e1);
                v2 = softplus_f(v2 + e0); v3 = softplus_f(v3 + e1);
            }
            *(__half2*)&out[(size_t)row * Nout + col] = __floats2half2_rn(v0, v1);
            *(__half2*)&out[(size_t)(row + 8) * Nout + col] =
                __floats2half2_rn(v2, v3);
        }
    }
}

// ---------------------------------------------------------------------------
// Chunked scan, half2 layout: 8 lanes per (b,d) pair, 2 states per lane,
// 4 pairs per warp (adjacent d) -> full 128B line per tensor per timestep.
// ---------------------------------------------------------------------------
__global__ __launch_bounds__(256)
void scan_pass1(const __half* __restrict__ Uh, const float* __restrict__ log_A,
                const __half* __restrict__ dt, const __half* __restrict__ Bt,
                float* __restrict__ P, float* __restrict__ H)
{
    const int tid = threadIdx.x;
    const int lane = tid & 31;
    const int warp = tid >> 5;
    const int pr = lane >> 3;            // pair within warp (0..3)
    const int nh = lane & 7;             // n-half index: states 2nh, 2nh+1
    const int p = blockIdx.x * 32 + warp * 4 + pr;   // (b,d) pair
    const int c = blockIdx.y;
    const int b = p >> 10;
    const int d = p & 1023;

    const float A0 = -expf(log_A[d * N_SZ + 2 * nh]);
    const float A1 = -expf(log_A[d * N_SZ + 2 * nh + 1]);
    const float iA0 = 1.0f / A0, iA1 = 1.0f / A1;

    size_t base = (size_t)b * L_SZ * D_SZ + (size_t)c * CL * D_SZ + d;
    const __half* dtp = dt + base;
    const __half* up  = Uh + base;
    const __half2* bp = (const __half2*)Bt + base * 8 + nh;

    float h0 = 0.0f, h1 = 0.0f, ap0 = 1.0f, ap1 = 1.0f;
#pragma unroll 4
    for (int t = 0; t < CL; ++t) {
        float dtv = __half2float(*dtp);
        float uv  = __half2float(*up);
        float2 bv = __half22float2(*bp);
        float a0 = __expf(dtv * A0);
        float a1 = __expf(dtv * A1);
        h0 = fmaf(a0, h0, (a0 - 1.0f) * iA0 * bv.x * uv);
        h1 = fmaf(a1, h1, (a1 - 1.0f) * iA1 * bv.y * uv);
        ap0 *= a0; ap1 *= a1;
        dtp += D_SZ; up += D_SZ; bp += D_SZ * 8;
    }
    const int idx2 = (p * NC + c) * 8 + nh;
    ((float2*)P)[idx2] = make_float2(ap0, ap1);
    ((float2*)H)[idx2] = make_float2(h0, h1);
}

__global__ __launch_bounds__(256)
void scan_chain(const float* __restrict__ P, const float* __restrict__ H,
                float* __restrict__ hs)
{
    const int id = blockIdx.x * blockDim.x + threadIdx.x;
    const int p = id >> 4;
    const int n = id & 15;
    float h = 0.0f;
#pragma unroll
    for (int c = 0; c < NC; ++c) {
        const int idx = (p * NC + c) * N_SZ + n;
        hs[idx] = h;
        h = fmaf(P[idx], h, H[idx]);
    }
}

__global__ __launch_bounds__(256)
void scan_pass2(const __half* __restrict__ Uh, const float* __restrict__ log_A,
                const float* __restrict__ D_skip,
                const __half* __restrict__ dt, const __half* __restrict__ Bt,
                const __half* __restrict__ Ct, const float* __restrict__ hs,
                float* __restrict__ out)
{
    const int tid = threadIdx.x;
    const int lane = tid & 31;
    const int warp = tid >> 5;
    const int pr = lane >> 3;
    const int nh = lane & 7;
    const int p = blockIdx.x * 32 + warp * 4 + pr;
    const int c = blockIdx.y;
    const int b = p >> 10;
    const int d = p & 1023;

    const float A0 = -expf(log_A[d * N_SZ + 2 * nh]);
    const float A1 = -expf(log_A[d * N_SZ + 2 * nh + 1]);
    const float iA0 = 1.0f / A0, iA1 = 1.0f / A1;
    const float Dsk = D_skip[d];

    size_t base = (size_t)b * L_SZ * D_SZ + (size_t)c * CL * D_SZ + d;
    const __half* dtp = dt + base;
    const __half* up  = Uh + base;
    float* op         = out + base;
    const __half2* bp = (const __half2*)Bt + base * 8 + nh;
    const __half2* cp = (const __half2*)Ct + base * 8 + nh;

    float2 h2 = ((const float2*)hs)[(p * NC + c) * 8 + nh];
    float h0 = h2.x, h1 = h2.y;
#pragma unroll 4
    for (int t = 0; t < CL; ++t) {
        float dtv = __half2float(*dtp);
        float uv  = __half2float(*up);
        float2 bv = __half22float2(*bp);
        float2 cv = __half22float2(*cp);
        float a0 = __expf(dtv * A0);
        float a1 = __expf(dtv * A1);
        h0 = fmaf(a0, h0, (a0 - 1.0f) * iA0 * bv.x * uv);
        h1 = fmaf(a1, h1, (a1 - 1.0f) * iA1 * bv.y * uv);
        float prod = fmaf(cv.x, h0, cv.y * h1);
        prod += __shfl_xor_sync(0xffffffffu, prod, 1);
        prod += __shfl_xor_sync(0xffffffffu, prod, 2);
        prod += __shfl_xor_sync(0xffffffffu, prod, 4);
        if (nh == 0) *op = fmaf(Dsk, uv, prod);
        dtp += D_SZ; up += D_SZ; op += D_SZ;
        bp += D_SZ * 8; cp += D_SZ * 8;
    }
}

// ---------------------------------------------------------------------------
// Launch (R8 schedule): s1: f2h_WB -> evWB, f2h_WC, gemm_C -> evC
// s0: f2h_u, f2h_Wdt, gemm_dt, [evWB] gemm_B, pass1, chain, [evC] pass2
// ---------------------------------------------------------------------------
extern "C" void kernel_launch(void* const* d_in, const int* in_sizes, int n_in,
                              void* d_out, int out_size)
{
    const float* u       = (const float*)d_in[0];
    const float* log_A   = (const float*)d_in[1];
    const float* D_skip  = (const float*)d_in[2];
    const float* dt_bias = (const float*)d_in[3];
    const float* W_dt    = (const float*)d_in[4];
    const float* b_dt    = (const float*)d_in[5];
    const float* W_B     = (const float*)d_in[6];
    const float* b_B     = (const float*)d_in[7];
    const float* W_C     = (const float*)d_in[8];
    const float* b_C     = (const float*)d_in[9];
    float* out = (float*)d_out;

    float *P, *H, *hs;
    __half *dt_buf, *B_buf, *C_buf, *Uh, *Wdth, *WBh, *WCh;
    cudaGetSymbolAddress((void**)&dt_buf, g_dt);
    cudaGetSymbolAddress((void**)&B_buf, g_Bt);
    cudaGetSymbolAddress((void**)&C_buf, g_Ct);
    cudaGetSymbolAddress((void**)&Uh, g_Uh);
    cudaGetSymbolAddress((void**)&Wdth, g_Wdth);
    cudaGetSymbolAddress((void**)&WBh, g_WBh);
    cudaGetSymbolAddress((void**)&WCh, g_WCh);
    cudaGetSymbolAddress((void**)&P, g_P);
    cudaGetSymbolAddress((void**)&H, g_H);
    cudaGetSymbolAddress((void**)&hs, g_hs);

    static cudaStream_t s1 = nullptr;
    static cudaEvent_t evRoot = nullptr, evWB = nullptr, evC = nullptr,
                       evDone = nullptr;
    if (!s1) {
        cudaStreamCreateWithFlags(&s1, cudaStreamNonBlocking);
        cudaEventCreateWithFlags(&evRoot, cudaEventDisableTiming);
        cudaEventCreateWithFlags(&evWB, cudaEventDisableTiming);
        cudaEventCreateWithFlags(&evC, cudaEventDisableTiming);
        cudaEventCreateWithFlags(&evDone, cudaEventDisableTiming);
        cudaFuncSetAttribute(gemm_mma_h,
                             cudaFuncAttributeMaxDynamicSharedMemorySize,
                             GEMM_SMEM);
    }

    const int n4_big = (int)((size_t)NOUT_BC * K_DIM / 4);

    // fork s1
    cudaEventRecord(evRoot, 0);
    cudaStreamWaitEvent(s1, evRoot, 0);

    // ---- side stream: WB convert, WC convert, C GEMM ----
    f2h_kernel<<<(n4_big / 2 + 255) / 256, 256, 0, s1>>>(W_B, WBh, n4_big);
    cudaEventRecord(evWB, s1);
    f2h_kernel<<<(n4_big / 2 + 255) / 256, 256, 0, s1>>>(W_C, WCh, n4_big);
    gemm_mma_h<<<dim3(NOUT_BC / 128, M_TOT / 128), 128, GEMM_SMEM, s1>>>(
        Uh, WCh, b_C, nullptr, C_buf, NOUT_BC, 1);
    cudaEventRecord(evC, s1);

    // ---- main stream ----
    f2h_kernel<<<(M_TOT * K_DIM / 8 + 255) / 256, 256>>>(u, Uh,
                                                         M_TOT * K_DIM / 4);
    f2h_kernel<<<(D_SZ * K_DIM / 8 + 255) / 256, 256>>>(W_dt, Wdth,
                                                        D_SZ * K_DIM / 4);
    gemm_mma_h<<<dim3(D_SZ / 128, M_TOT / 128), 128, GEMM_SMEM>>>(
        Uh, Wdth, b_dt, dt_bias, dt_buf, D_SZ, 0);
    cudaStreamWaitEvent(0, evWB, 0);
    gemm_mma_h<<<dim3(NOUT_BC / 128, M_TOT / 128), 128, GEMM_SMEM>>>(
        Uh, WBh, b_B, nullptr, B_buf, NOUT_BC, 1);

    dim3 sgrid(B_SZ * D_SZ / 32, NC);
    scan_pass1<<<sgrid, 256>>>(Uh, log_A, dt_buf, B_buf, P, H);
    scan_chain<<<B_SZ * D_SZ * N_SZ / 256, 256>>>(P, H, hs);

    // join: pass2 needs Ct
    cudaStreamWaitEvent(0, evC, 0);
    scan_pass2<<<sgrid, 256>>>(Uh, log_A, D_skip, dt_buf, B_buf, C_buf, hs, out);
}

// round 13
// speedup vs baseline: 1.1237x; 1.0652x over previous
#include <cuda_runtime.h>
#include <cuda_fp16.h>
#include <cstdint>
#include <math.h>

// Problem constants
#define B_SZ 2
#define L_SZ 2048
#define D_SZ 1024
#define N_SZ 16
#define M_TOT (B_SZ * L_SZ)      // 4096
#define K_DIM D_SZ               // 1024
#define NOUT_BC (D_SZ * N_SZ)    // 16384

#define NC 16                    // scan chunks
#define CL (L_SZ / NC)           // 128

// Scratch (device globals: allocation-free rule)
__device__ __half g_dt[M_TOT * D_SZ];                       // 8 MB
__device__ __half g_Bt[(size_t)M_TOT * NOUT_BC];            // 128 MB
__device__ __half g_Ct[(size_t)M_TOT * NOUT_BC];            // 128 MB
// fp16 copies of U and weights
__device__ __half g_Uh[M_TOT * K_DIM];                      // 8 MB
__device__ __half g_Wdth[D_SZ * K_DIM];                     // 2 MB
__device__ __half g_WBh[(size_t)NOUT_BC * K_DIM];           // 32 MB
__device__ __half g_WCh[(size_t)NOUT_BC * K_DIM];           // 32 MB
// scan chunk state
__device__ float g_P[B_SZ * D_SZ * NC * N_SZ];              // 2 MB
__device__ float g_H[B_SZ * D_SZ * NC * N_SZ];              // 2 MB
__device__ float g_hs[B_SZ * D_SZ * NC * N_SZ];             // 2 MB

// ---------------------------------------------------------------------------
// helpers
// ---------------------------------------------------------------------------
__device__ __forceinline__ uint32_t smem_u32(const void* p) {
    uint32_t a;
    asm("{ .reg .u64 t; cvta.to.shared.u64 t, %1; cvt.u32.u64 %0, t; }"
        : "=r"(a) : "l"(p));
    return a;
}
__device__ __forceinline__ void cp_async16(uint32_t dst, const void* src) {
    asm volatile("cp.async.cg.shared.global [%0], [%1], 16;"
                 :: "r"(dst), "l"(src) : "memory");
}
__device__ __forceinline__ float softplus_f(float x) {
    return (x > 20.0f) ? x : log1pf(expf(x));
}
__device__ __forceinline__ void mma_f16(float* c, const uint32_t* a,
                                        const uint32_t* b) {
    asm volatile(
        "mma.sync.aligned.m16n8k16.row.col.f32.f16.f16.f32 "
        "{%0,%1,%2,%3}, {%4,%5,%6,%7}, {%8,%9}, {%0,%1,%2,%3};"
        : "+f"(c[0]), "+f"(c[1]), "+f"(c[2]), "+f"(c[3])
        : "r"(a[0]), "r"(a[1]), "r"(a[2]), "r"(a[3]), "r"(b[0]), "r"(b[1]));
}
__device__ __forceinline__ void ldsm_x4(uint32_t* r, uint32_t addr) {
    asm volatile("ldmatrix.sync.aligned.m8n8.x4.shared.b16 {%0,%1,%2,%3}, [%4];"
                 : "=r"(r[0]), "=r"(r[1]), "=r"(r[2]), "=r"(r[3]) : "r"(addr));
}

// ---------------------------------------------------------------------------
// fp32 -> fp16 (rne) conversion pre-pass (memory-bound, 2 float4 per thread)
// ---------------------------------------------------------------------------
__global__ __launch_bounds__(256)
void f2h_kernel(const float* __restrict__ in, __half* __restrict__ out, int n4) {
    int i = (blockIdx.x * blockDim.x + threadIdx.x) * 2;
    if (i + 1 < n4) {
        float4 v0 = ((const float4*)in)[i];
        float4 v1 = ((const float4*)in)[i + 1];
        ((__half2*)out)[2 * i]     = __floats2half2_rn(v0.x, v0.y);
        ((__half2*)out)[2 * i + 1] = __floats2half2_rn(v0.z, v0.w);
        ((__half2*)out)[2 * i + 2] = __floats2half2_rn(v1.x, v1.y);
        ((__half2*)out)[2 * i + 3] = __floats2half2_rn(v1.z, v1.w);
    } else if (i < n4) {
        float4 v0 = ((const float4*)in)[i];
        ((__half2*)out)[2 * i]     = __floats2half2_rn(v0.x, v0.y);
        ((__half2*)out)[2 * i + 1] = __floats2half2_rn(v0.z, v0.w);
    }
}

// ---------------------------------------------------------------------------
// GEMM (mma.sync fp16 m16n8k16 + ldmatrix + 3-stage cp.async pipeline)
//   mode 0: half out, softplus(val + bias + bias2)   (dt path)
//   mode 1: half out, val + bias                     (B/C path)
// 128 threads (4 warps), CTA tile 128x128, BK=64, one barrier per k-tile.
// ---------------------------------------------------------------------------
#define HSTRIDE 72               // halves per row (64 + 8 pad); 144B rows
#define TILE_B (128 * HSTRIDE * 2)       // bytes per tile = 18432
#define NSTAGE 3
#define GEMM_SMEM (NSTAGE * 2 * TILE_B)  // 110592 bytes

__global__ __launch_bounds__(128, 2)
void gemm_mma_h(const __half* __restrict__ U, const __half* __restrict__ W,
                const float* __restrict__ bias, const float* __restrict__ bias2,
                __half* __restrict__ out, int Nout, int mode)
{
    extern __shared__ char smc[];
    const int tid = threadIdx.x;
    const int wid = tid >> 5;
    const int lane = tid & 31;
    const int bx = blockIdx.x;      // N tile
    const int by = blockIdx.y;      // M tile
    const int m0 = (wid & 1) * 64, n0 = (wid >> 1) * 64;
    const int g = lane >> 2, t4 = lane & 3;

    const __half* Ag = U + (size_t)(by * 128) * K_DIM;
    const __half* Bg = W + (size_t)(bx * 128) * K_DIM;

    const int sel = lane >> 3;
    const int lr  = lane & 7;
    uint32_t aoff[4];
#pragma unroll
    for (int mt = 0; mt < 4; ++mt) {
        int row = m0 + mt * 16 + lr + (sel & 1) * 8;
        int kh  = (sel >> 1) * 8;
        aoff[mt] = (uint32_t)((row * HSTRIDE + kh) * 2);
    }
    uint32_t boff[4];
#pragma unroll
    for (int ntp = 0; ntp < 4; ++ntp) {
        int row = n0 + (2 * ntp + (sel >> 1)) * 8 + lr;
        int kh  = (sel & 1) * 8;
        boff[ntp] = (uint32_t)((row * HSTRIDE + kh) * 2);
    }

    float acc[4][8][4];
#pragma unroll
    for (int mt = 0; mt < 4; ++mt)
#pragma unroll
        for (int nt = 0; nt < 8; ++nt)
#pragma unroll
            for (int j = 0; j < 4; ++j) acc[mt][nt][j] = 0.0f;

    const int NK = K_DIM / 64;      // 16 k-tiles
    const uint32_t sm_u = smem_u32(smc);

    auto issue = [&](int it, int stg) {
        char* As = smc + stg * 2 * TILE_B;
        char* Bs = As + TILE_B;
        const int kc = it * 64;
#pragma unroll
        for (int i = 0; i < 8; ++i) {
            int id = tid + i * 128;
            int row = id >> 3;
            int q = id & 7;
            cp_async16(smem_u32(As + (row * HSTRIDE + q * 8) * 2),
                       Ag + (size_t)row * K_DIM + kc + q * 8);
            cp_async16(smem_u32(Bs + (row * HSTRIDE + q * 8) * 2),
                       Bg + (size_t)row * K_DIM + kc + q * 8);
        }
        asm volatile("cp.async.commit_group;" ::: "memory");
    };

    issue(0, 0);
    issue(1, 1);
    for (int it = 0; it < NK; ++it) {
        if (it < NK - 1) {
            asm volatile("cp.async.wait_group 1;" ::: "memory");
        } else {
            asm volatile("cp.async.wait_group 0;" ::: "memory");
        }
        __syncthreads();
        if (it + 2 < NK) issue(it + 2, (it + 2) % NSTAGE);

        const uint32_t As_u = sm_u + (uint32_t)((it % NSTAGE) * 2 * TILE_B);
        const uint32_t Bs_u = As_u + (uint32_t)TILE_B;
#pragma unroll
        for (int ks = 0; ks < 4; ++ks) {
            const uint32_t kb = ks * 32;
            uint32_t a[4][4], b[4][4];
#pragma unroll
            for (int mt = 0; mt < 4; ++mt)
                ldsm_x4(a[mt], As_u + aoff[mt] + kb);
#pragma unroll
            for (int ntp = 0; ntp < 4; ++ntp)
                ldsm_x4(b[ntp], Bs_u + boff[ntp] + kb);
#pragma unroll
            for (int mt = 0; mt < 4; ++mt)
#pragma unroll
                for (int nt = 0; nt < 8; ++nt)
                    mma_f16(acc[mt][nt], a[mt], &b[nt >> 1][(nt & 1) * 2]);
        }
    }

    // Epilogue (half output, bias / softplus fused)
#pragma unroll
    for (int nt = 0; nt < 8; ++nt) {
        const int col = bx * 128 + n0 + nt * 8 + t4 * 2;
        float b0 = bias[col], b1 = bias[col + 1];
        float e0 = 0.f, e1 = 0.f;
        if (mode == 0) { e0 = bias2[col]; e1 = bias2[col + 1]; }
#pragma unroll
        for (int mt = 0; mt < 4; ++mt) {
            const int row = by * 128 + m0 + mt * 16 + g;
            float v0 = acc[mt][nt][0] + b0;
            float v1 = acc[mt][nt][1] + b1;
            float v2 = acc[mt][nt][2] + b0;
            float v3 = acc[mt][nt][3] + b1;
            if (mode == 0) {
                v0 = softplus_f(v0 + e0); v1 = softplus_f(v1 + e1);
                v2 = softplus_f(v2 + e0); v3 = softplus_f(v3 + e1);
            }
            *(__half2*)&out[(size_t)row * Nout + col] = __floats2half2_rn(v0, v1);
            *(__half2*)&out[(size_t)(row + 8) * Nout + col] =
                __floats2half2_rn(v2, v3);
        }
    }
}

// ---------------------------------------------------------------------------
// Chunked scan (R8 layout: 16 lanes per (b,d) pair, 2 pairs per warp),
// NC=16 chunks for 2x parallelism. dt/Bt/Ct fp16; u fp32; state math fp32.
// ---------------------------------------------------------------------------
__global__ __launch_bounds__(256)
void scan_pass1(const float* __restrict__ u, const float* __restrict__ log_A,
                const __half* __restrict__ dt, const __half* __restrict__ Bt,
                float* __restrict__ P, float* __restrict__ H)
{
    const int tid = threadIdx.x;
    const int lane = tid & 31;
    const int half = lane >> 4;
    const int n = lane & 15;
    const int warp = tid >> 5;
    const int p = blockIdx.x * 16 + warp * 2 + half;
    const int c = blockIdx.y;
    const int b = p >> 10;
    const int d = p & 1023;

    const float A = -expf(log_A[d * N_SZ + n]);
    const float invA = 1.0f / A;

    size_t base = (size_t)b * L_SZ * D_SZ + (size_t)c * CL * D_SZ + d;
    const __half* dtp = dt + base;
    const float* up  = u + base;
    const __half* bp = Bt + base * N_SZ + n;

    float h = 0.0f, aprod = 1.0f;
#pragma unroll 4
    for (int t = 0; t < CL; ++t) {
        float a = __expf(__half2float(*dtp) * A);
        float x = (a - 1.0f) * invA * __half2float(*bp) * (*up);
        h = fmaf(a, h, x);
        aprod *= a;
        dtp += D_SZ; up += D_SZ; bp += (size_t)D_SZ * N_SZ;
    }
    const int idx = (p * NC + c) * N_SZ + n;
    P[idx] = aprod;
    H[idx] = h;
}

__global__ __launch_bounds__(256)
void scan_chain(const float* __restrict__ P, const float* __restrict__ H,
                float* __restrict__ hs)
{
    const int id = blockIdx.x * blockDim.x + threadIdx.x;
    const int p = id >> 4;
    const int n = id & 15;
    float h = 0.0f;
#pragma unroll
    for (int c = 0; c < NC; ++c) {
        const int idx = (p * NC + c) * N_SZ + n;
        hs[idx] = h;
        h = fmaf(P[idx], h, H[idx]);
    }
}

__global__ __launch_bounds__(256)
void scan_pass2(const float* __restrict__ u, const float* __restrict__ log_A,
                const float* __restrict__ D_skip,
                const __half* __restrict__ dt, const __half* __restrict__ Bt,
                const __half* __restrict__ Ct, const float* __restrict__ hs,
                float* __restrict__ out)
{
    const int tid = threadIdx.x;
    const int lane = tid & 31;
    const int half = lane >> 4;
    const int n = lane & 15;
    const int warp = tid >> 5;
    const int p = blockIdx.x * 16 + warp * 2 + half;
    const int c = blockIdx.y;
    const int b = p >> 10;
    const int d = p & 1023;

    const float A = -expf(log_A[d * N_SZ + n]);
    const float invA = 1.0f / A;
    const float Dsk = D_skip[d];

    size_t base = (size_t)b * L_SZ * D_SZ + (size_t)c * CL * D_SZ + d;
    const __half* dtp = dt + base;
    const float* up  = u + base;
    float* op        = out + base;
    const __half* bp = Bt + base * N_SZ + n;
    const __half* cp = Ct + base * N_SZ + n;

    float h = hs[(p * NC + c) * N_SZ + n];
#pragma unroll 4
    for (int t = 0; t < CL; ++t) {
        float uv = *up;
        float a = __expf(__half2float(*dtp) * A);
        float x = (a - 1.0f) * invA * __half2float(*bp) * uv;
        h = fmaf(a, h, x);
        float prod = __half2float(*cp) * h;
        prod += __shfl_xor_sync(0xffffffffu, prod, 1);
        prod += __shfl_xor_sync(0xffffffffu, prod, 2);
        prod += __shfl_xor_sync(0xffffffffu, prod, 4);
        prod += __shfl_xor_sync(0xffffffffu, prod, 8);
        if (n == 0) *op = fmaf(Dsk, uv, prod);
        dtp += D_SZ; up += D_SZ; op += D_SZ;
        bp += (size_t)D_SZ * N_SZ; cp += (size_t)D_SZ * N_SZ;
    }
}

// ---------------------------------------------------------------------------
// Launch (R8 schedule): s1: f2h_WB -> evWB, f2h_WC, gemm_C -> evC
// s0: f2h_u, f2h_Wdt, gemm_dt, [evWB] gemm_B, pass1, chain, [evC] pass2
// ---------------------------------------------------------------------------
extern "C" void kernel_launch(void* const* d_in, const int* in_sizes, int n_in,
                              void* d_out, int out_size)
{
    const float* u       = (const float*)d_in[0];
    const float* log_A   = (const float*)d_in[1];
    const float* D_skip  = (const float*)d_in[2];
    const float* dt_bias = (const float*)d_in[3];
    const float* W_dt    = (const float*)d_in[4];
    const float* b_dt    = (const float*)d_in[5];
    const float* W_B     = (const float*)d_in[6];
    const float* b_B     = (const float*)d_in[7];
    const float* W_C     = (const float*)d_in[8];
    const float* b_C     = (const float*)d_in[9];
    float* out = (float*)d_out;

    float *P, *H, *hs;
    __half *dt_buf, *B_buf, *C_buf, *Uh, *Wdth, *WBh, *WCh;
    cudaGetSymbolAddress((void**)&dt_buf, g_dt);
    cudaGetSymbolAddress((void**)&B_buf, g_Bt);
    cudaGetSymbolAddress((void**)&C_buf, g_Ct);
    cudaGetSymbolAddress((void**)&Uh, g_Uh);
    cudaGetSymbolAddress((void**)&Wdth, g_Wdth);
    cudaGetSymbolAddress((void**)&WBh, g_WBh);
    cudaGetSymbolAddress((void**)&WCh, g_WCh);
    cudaGetSymbolAddress((void**)&P, g_P);
    cudaGetSymbolAddress((void**)&H, g_H);
    cudaGetSymbolAddress((void**)&hs, g_hs);

    static cudaStream_t s1 = nullptr;
    static cudaEvent_t evRoot = nullptr, evWB = nullptr, evC = nullptr,
                       evDone = nullptr;
    if (!s1) {
        cudaStreamCreateWithFlags(&s1, cudaStreamNonBlocking);
        cudaEventCreateWithFlags(&evRoot, cudaEventDisableTiming);
        cudaEventCreateWithFlags(&evWB, cudaEventDisableTiming);
        cudaEventCreateWithFlags(&evC, cudaEventDisableTiming);
        cudaEventCreateWithFlags(&evDone, cudaEventDisableTiming);
        cudaFuncSetAttribute(gemm_mma_h,
                             cudaFuncAttributeMaxDynamicSharedMemorySize,
                             GEMM_SMEM);
    }

    const int n4_big = (int)((size_t)NOUT_BC * K_DIM / 4);

    // fork s1
    cudaEventRecord(evRoot, 0);
    cudaStreamWaitEvent(s1, evRoot, 0);

    // ---- side stream: WB convert, WC convert, C GEMM ----
    f2h_kernel<<<(n4_big / 2 + 255) / 256, 256, 0, s1>>>(W_B, WBh, n4_big);
    cudaEventRecord(evWB, s1);
    f2h_kernel<<<(n4_big / 2 + 255) / 256, 256, 0, s1>>>(W_C, WCh, n4_big);
    gemm_mma_h<<<dim3(NOUT_BC / 128, M_TOT / 128), 128, GEMM_SMEM, s1>>>(
        Uh, WCh, b_C, nullptr, C_buf, NOUT_BC, 1);
    cudaEventRecord(evC, s1);

    // ---- main stream ----
    f2h_kernel<<<(M_TOT * K_DIM / 8 + 255) / 256, 256>>>(u, Uh,
                                                         M_TOT * K_DIM / 4);
    f2h_kernel<<<(D_SZ * K_DIM / 8 + 255) / 256, 256>>>(W_dt, Wdth,
                                                        D_SZ * K_DIM / 4);
    gemm_mma_h<<<dim3(D_SZ / 128, M_TOT / 128), 128, GEMM_SMEM>>>(
        Uh, Wdth, b_dt, dt_bias, dt_buf, D_SZ, 0);
    cudaStreamWaitEvent(0, evWB, 0);
    gemm_mma_h<<<dim3(NOUT_BC / 128, M_TOT / 128), 128, GEMM_SMEM>>>(
        Uh, WBh, b_B, nullptr, B_buf, NOUT_BC, 1);

    dim3 sgrid(B_SZ * D_SZ / 16, NC);
    scan_pass1<<<sgrid, 256>>>(u, log_A, dt_buf, B_buf, P, H);
    scan_chain<<<B_SZ * D_SZ * N_SZ / 256, 256>>>(P, H, hs);

    // join: pass2 needs Ct
    cudaStreamWaitEvent(0, evC, 0);
    scan_pass2<<<sgrid, 256>>>(u, log_A, D_skip, dt_buf, B_buf, C_buf, hs, out);
}

// round 14
// speedup vs baseline: 1.1310x; 1.0065x over previous
#include <cuda_runtime.h>
#include <cuda_fp16.h>
#include <cstdint>
#include <math.h>

// Problem constants
#define B_SZ 2
#define L_SZ 2048
#define D_SZ 1024
#define N_SZ 16
#define M_TOT (B_SZ * L_SZ)      // 4096
#define K_DIM D_SZ               // 1024
#define NOUT_BC (D_SZ * N_SZ)    // 16384

#define NC 32                    // scan chunks
#define CL (L_SZ / NC)           // 64

// Scratch (device globals: allocation-free rule)
__device__ __half g_dt[M_TOT * D_SZ];                       // 8 MB
__device__ __half g_Bt[(size_t)M_TOT * NOUT_BC];            // 128 MB
__device__ __half g_Ct[(size_t)M_TOT * NOUT_BC];            // 128 MB
// fp16 copies of U and weights
__device__ __half g_Uh[M_TOT * K_DIM];                      // 8 MB
__device__ __half g_Wdth[D_SZ * K_DIM];                     // 2 MB
__device__ __half g_WBh[(size_t)NOUT_BC * K_DIM];           // 32 MB
__device__ __half g_WCh[(size_t)NOUT_BC * K_DIM];           // 32 MB
// scan chunk state
__device__ float g_P[B_SZ * D_SZ * NC * N_SZ];              // 4 MB
__device__ float g_H[B_SZ * D_SZ * NC * N_SZ];              // 4 MB

// ---------------------------------------------------------------------------
// helpers
// ---------------------------------------------------------------------------
__device__ __forceinline__ uint32_t smem_u32(const void* p) {
    uint32_t a;
    asm("{ .reg .u64 t; cvta.to.shared.u64 t, %1; cvt.u32.u64 %0, t; }"
        : "=r"(a) : "l"(p));
    return a;
}
__device__ __forceinline__ void cp_async16(uint32_t dst, const void* src) {
    asm volatile("cp.async.cg.shared.global [%0], [%1], 16;"
                 :: "r"(dst), "l"(src) : "memory");
}
__device__ __forceinline__ float softplus_f(float x) {
    return (x > 20.0f) ? x : log1pf(expf(x));
}
__device__ __forceinline__ void mma_f16(float* c, const uint32_t* a,
                                        const uint32_t* b) {
    asm volatile(
        "mma.sync.aligned.m16n8k16.row.col.f32.f16.f16.f32 "
        "{%0,%1,%2,%3}, {%4,%5,%6,%7}, {%8,%9}, {%0,%1,%2,%3};"
        : "+f"(c[0]), "+f"(c[1]), "+f"(c[2]), "+f"(c[3])
        : "r"(a[0]), "r"(a[1]), "r"(a[2]), "r"(a[3]), "r"(b[0]), "r"(b[1]));
}
__device__ __forceinline__ void ldsm_x4(uint32_t* r, uint32_t addr) {
    asm volatile("ldmatrix.sync.aligned.m8n8.x4.shared.b16 {%0,%1,%2,%3}, [%4];"
                 : "=r"(r[0]), "=r"(r[1]), "=r"(r[2]), "=r"(r[3]) : "r"(addr));
}

// ---------------------------------------------------------------------------
// fp32 -> fp16 (rne) conversion pre-pass (memory-bound, 2 float4 per thread)
// ---------------------------------------------------------------------------
__global__ __launch_bounds__(256)
void f2h_kernel(const float* __restrict__ in, __half* __restrict__ out, int n4) {
    int i = (blockIdx.x * blockDim.x + threadIdx.x) * 2;
    if (i + 1 < n4) {
        float4 v0 = ((const float4*)in)[i];
        float4 v1 = ((const float4*)in)[i + 1];
        ((__half2*)out)[2 * i]     = __floats2half2_rn(v0.x, v0.y);
        ((__half2*)out)[2 * i + 1] = __floats2half2_rn(v0.z, v0.w);
        ((__half2*)out)[2 * i + 2] = __floats2half2_rn(v1.x, v1.y);
        ((__half2*)out)[2 * i + 3] = __floats2half2_rn(v1.z, v1.w);
    } else if (i < n4) {
        float4 v0 = ((const float4*)in)[i];
        ((__half2*)out)[2 * i]     = __floats2half2_rn(v0.x, v0.y);
        ((__half2*)out)[2 * i + 1] = __floats2half2_rn(v0.z, v0.w);
    }
}

// ---------------------------------------------------------------------------
// GEMM (mma.sync fp16 m16n8k16 + ldmatrix + 3-stage cp.async pipeline)
//   mode 0: half out, softplus(val + bias + bias2)   (dt path)
//   mode 1: half out, val + bias                     (B/C path)
// 128 threads (4 warps), CTA tile 128x128, BK=64, one barrier per k-tile.
// ---------------------------------------------------------------------------
#define HSTRIDE 72               // halves per row (64 + 8 pad); 144B rows
#define TILE_B (128 * HSTRIDE * 2)       // bytes per tile = 18432
#define NSTAGE 3
#define GEMM_SMEM (NSTAGE * 2 * TILE_B)  // 110592 bytes

__global__ __launch_bounds__(128, 2)
void gemm_mma_h(const __half* __restrict__ U, const __half* __restrict__ W,
                const float* __restrict__ bias, const float* __restrict__ bias2,
                __half* __restrict__ out, int Nout, int mode)
{
    extern __shared__ char smc[];
    const int tid = threadIdx.x;
    const int wid = tid >> 5;
    const int lane = tid & 31;
    const int bx = blockIdx.x;      // N tile
    const int by = blockIdx.y;      // M tile
    const int m0 = (wid & 1) * 64, n0 = (wid >> 1) * 64;
    const int g = lane >> 2, t4 = lane & 3;

    const __half* Ag = U + (size_t)(by * 128) * K_DIM;
    const __half* Bg = W + (size_t)(bx * 128) * K_DIM;

    const int sel = lane >> 3;
    const int lr  = lane & 7;
    uint32_t aoff[4];
#pragma unroll
    for (int mt = 0; mt < 4; ++mt) {
        int row = m0 + mt * 16 + lr + (sel & 1) * 8;
        int kh  = (sel >> 1) * 8;
        aoff[mt] = (uint32_t)((row * HSTRIDE + kh) * 2);
    }
    uint32_t boff[4];
#pragma unroll
    for (int ntp = 0; ntp < 4; ++ntp) {
        int row = n0 + (2 * ntp + (sel >> 1)) * 8 + lr;
        int kh  = (sel & 1) * 8;
        boff[ntp] = (uint32_t)((row * HSTRIDE + kh) * 2);
    }

    float acc[4][8][4];
#pragma unroll
    for (int mt = 0; mt < 4; ++mt)
#pragma unroll
        for (int nt = 0; nt < 8; ++nt)
#pragma unroll
            for (int j = 0; j < 4; ++j) acc[mt][nt][j] = 0.0f;

    const int NK = K_DIM / 64;      // 16 k-tiles
    const uint32_t sm_u = smem_u32(smc);

    auto issue = [&](int it, int stg) {
        char* As = smc + stg * 2 * TILE_B;
        char* Bs = As + TILE_B;
        const int kc = it * 64;
#pragma unroll
        for (int i = 0; i < 8; ++i) {
            int id = tid + i * 128;
            int row = id >> 3;
            int q = id & 7;
            cp_async16(smem_u32(As + (row * HSTRIDE + q * 8) * 2),
                       Ag + (size_t)row * K_DIM + kc + q * 8);
            cp_async16(smem_u32(Bs + (row * HSTRIDE + q * 8) * 2),
                       Bg + (size_t)row * K_DIM + kc + q * 8);
        }
        asm volatile("cp.async.commit_group;" ::: "memory");
    };

    issue(0, 0);
    issue(1, 1);
    for (int it = 0; it < NK; ++it) {
        if (it < NK - 1) {
            asm volatile("cp.async.wait_group 1;" ::: "memory");
        } else {
            asm volatile("cp.async.wait_group 0;" ::: "memory");
        }
        __syncthreads();
        if (it + 2 < NK) issue(it + 2, (it + 2) % NSTAGE);

        const uint32_t As_u = sm_u + (uint32_t)((it % NSTAGE) * 2 * TILE_B);
        const uint32_t Bs_u = As_u + (uint32_t)TILE_B;
#pragma unroll
        for (int ks = 0; ks < 4; ++ks) {
            const uint32_t kb = ks * 32;
            uint32_t a[4][4], b[4][4];
#pragma unroll
            for (int mt = 0; mt < 4; ++mt)
                ldsm_x4(a[mt], As_u + aoff[mt] + kb);
#pragma unroll
            for (int ntp = 0; ntp < 4; ++ntp)
                ldsm_x4(b[ntp], Bs_u + boff[ntp] + kb);
#pragma unroll
            for (int mt = 0; mt < 4; ++mt)
#pragma unroll
                for (int nt = 0; nt < 8; ++nt)
                    mma_f16(acc[mt][nt], a[mt], &b[nt >> 1][(nt & 1) * 2]);
        }
    }

    // Epilogue (half output, bias / softplus fused)
#pragma unroll
    for (int nt = 0; nt < 8; ++nt) {
        const int col = bx * 128 + n0 + nt * 8 + t4 * 2;
        float b0 = bias[col], b1 = bias[col + 1];
        float e0 = 0.f, e1 = 0.f;
        if (mode == 0) { e0 = bias2[col]; e1 = bias2[col + 1]; }
#pragma unroll
        for (int mt = 0; mt < 4; ++mt) {
            const int row = by * 128 + m0 + mt * 16 + g;
            float v0 = acc[mt][nt][0] + b0;
            float v1 = acc[mt][nt][1] + b1;
            float v2 = acc[mt][nt][2] + b0;
            float v3 = acc[mt][nt][3] + b1;
            if (mode == 0) {
                v0 = softplus_f(v0 + e0); v1 = softplus_f(v1 + e1);
                v2 = softplus_f(v2 + e0); v3 = softplus_f(v3 + e1);
            }
            *(__half2*)&out[(size_t)row * Nout + col] = __floats2half2_rn(v0, v1);
            *(__half2*)&out[(size_t)(row + 8) * Nout + col] =
                __floats2half2_rn(v2, v3);
        }
    }
}

// ---------------------------------------------------------------------------
// Chunked scan (16 lanes per (b,d) pair, 2 pairs per warp), NC=32.
// dt/Bt/Ct fp16; u fp32; state math fp32.
// ---------------------------------------------------------------------------
__global__ __launch_bounds__(256)
void scan_pass1(const float* __restrict__ u, const float* __restrict__ log_A,
                const __half* __restrict__ dt, const __half* __restrict__ Bt,
                float* __restrict__ P, float* __restrict__ H)
{
    const int tid = threadIdx.x;
    const int lane = tid & 31;
    const int half = lane >> 4;
    const int n = lane & 15;
    const int warp = tid >> 5;
    const int p = blockIdx.x * 16 + warp * 2 + half;
    const int c = blockIdx.y;
    const int b = p >> 10;
    const int d = p & 1023;

    const float A = -expf(log_A[d * N_SZ + n]);
    const float invA = 1.0f / A;

    size_t base = (size_t)b * L_SZ * D_SZ + (size_t)c * CL * D_SZ + d;
    const __half* dtp = dt + base;
    const float* up  = u + base;
    const __half* bp = Bt + base * N_SZ + n;

    float h = 0.0f, aprod = 1.0f;
#pragma unroll 4
    for (int t = 0; t < CL; ++t) {
        float a = __expf(__half2float(*dtp) * A);
        float x = (a - 1.0f) * invA * __half2float(*bp) * (*up);
        h = fmaf(a, h, x);
        aprod *= a;
        dtp += D_SZ; up += D_SZ; bp += (size_t)D_SZ * N_SZ;
    }
    const int idx = (p * NC + c) * N_SZ + n;
    P[idx] = aprod;
    H[idx] = h;
}

__global__ __launch_bounds__(256)
void scan_pass2(const float* __restrict__ u, const float* __restrict__ log_A,
                const float* __restrict__ D_skip,
                const __half* __restrict__ dt, const __half* __restrict__ Bt,
                const __half* __restrict__ Ct,
                const float* __restrict__ P, const float* __restrict__ H,
                float* __restrict__ out)
{
    const int tid = threadIdx.x;
    const int lane = tid & 31;
    const int half = lane >> 4;
    const int n = lane & 15;
    const int warp = tid >> 5;
    const int p = blockIdx.x * 16 + warp * 2 + half;
    const int c = blockIdx.y;
    const int b = p >> 10;
    const int d = p & 1023;

    const float A = -expf(log_A[d * N_SZ + n]);
    const float invA = 1.0f / A;
    const float Dsk = D_skip[d];

    // chain prologue: fold chunk summaries 0..c-1 (P/H are L2-resident, 4MB)
    float h = 0.0f;
    {
        const float* Pp = P + (p * NC) * N_SZ + n;
        const float* Hp = H + (p * NC) * N_SZ + n;
        for (int cc = 0; cc < c; ++cc) {
            h = fmaf(Pp[cc * N_SZ], h, Hp[cc * N_SZ]);
        }
    }

    size_t base = (size_t)b * L_SZ * D_SZ + (size_t)c * CL * D_SZ + d;
    const __half* dtp = dt + base;
    const float* up  = u + base;
    float* op        = out + base;
    const __half* bp = Bt + base * N_SZ + n;
    const __half* cp = Ct + base * N_SZ + n;

#pragma unroll 4
    for (int t = 0; t < CL; ++t) {
        float uv = *up;
        float a = __expf(__half2float(*dtp) * A);
        float x = (a - 1.0f) * invA * __half2float(*bp) * uv;
        h = fmaf(a, h, x);
        float prod = __half2float(*cp) * h;
        prod += __shfl_xor_sync(0xffffffffu, prod, 1);
        prod += __shfl_xor_sync(0xffffffffu, prod, 2);
        prod += __shfl_xor_sync(0xffffffffu, prod, 4);
        prod += __shfl_xor_sync(0xffffffffu, prod, 8);
        if (n == 0) *op = fmaf(Dsk, uv, prod);
        dtp += D_SZ; up += D_SZ; op += D_SZ;
        bp += (size_t)D_SZ * N_SZ; cp += (size_t)D_SZ * N_SZ;
    }
}

// ---------------------------------------------------------------------------
// Launch (R13 schedule + evU race fix, chain merged into pass2):
// s0: f2h_u -> evU, f2h_Wdt, gemm_dt, [evWB] gemm_B, pass1, [evC] pass2
// s1: f2h_WB -> evWB, f2h_WC, [evU] gemm_C -> evC
// ---------------------------------------------------------------------------
extern "C" void kernel_launch(void* const* d_in, const int* in_sizes, int n_in,
                              void* d_out, int out_size)
{
    const float* u       = (const float*)d_in[0];
    const float* log_A   = (const float*)d_in[1];
    const float* D_skip  = (const float*)d_in[2];
    const float* dt_bias = (const float*)d_in[3];
    const float* W_dt    = (const float*)d_in[4];
    const float* b_dt    = (const float*)d_in[5];
    const float* W_B     = (const float*)d_in[6];
    const float* b_B     = (const float*)d_in[7];
    const float* W_C     = (const float*)d_in[8];
    const float* b_C     = (const float*)d_in[9];
    float* out = (float*)d_out;

    float *P, *H;
    __half *dt_buf, *B_buf, *C_buf, *Uh, *Wdth, *WBh, *WCh;
    cudaGetSymbolAddress((void**)&dt_buf, g_dt);
    cudaGetSymbolAddress((void**)&B_buf, g_Bt);
    cudaGetSymbolAddress((void**)&C_buf, g_Ct);
    cudaGetSymbolAddress((void**)&Uh, g_Uh);
    cudaGetSymbolAddress((void**)&Wdth, g_Wdth);
    cudaGetSymbolAddress((void**)&WBh, g_WBh);
    cudaGetSymbolAddress((void**)&WCh, g_WCh);
    cudaGetSymbolAddress((void**)&P, g_P);
    cudaGetSymbolAddress((void**)&H, g_H);

    static cudaStream_t s1 = nullptr;
    static cudaEvent_t evRoot = nullptr, evU = nullptr, evWB = nullptr,
                       evC = nullptr;
    if (!s1) {
        cudaStreamCreateWithFlags(&s1, cudaStreamNonBlocking);
        cudaEventCreateWithFlags(&evRoot, cudaEventDisableTiming);
        cudaEventCreateWithFlags(&evU, cudaEventDisableTiming);
        cudaEventCreateWithFlags(&evWB, cudaEventDisableTiming);
        cudaEventCreateWithFlags(&evC, cudaEventDisableTiming);
        cudaFuncSetAttribute(gemm_mma_h,
                             cudaFuncAttributeMaxDynamicSharedMemorySize,
                             GEMM_SMEM);
    }

    const int n4_big = (int)((size_t)NOUT_BC * K_DIM / 4);

    // fork s1
    cudaEventRecord(evRoot, 0);
    cudaStreamWaitEvent(s1, evRoot, 0);

    // ---- s0: u convert first (Uh needed by all GEMMs) ----
    f2h_kernel<<<(M_TOT * K_DIM / 8 + 255) / 256, 256>>>(u, Uh,
                                                         M_TOT * K_DIM / 4);
    cudaEventRecord(evU, 0);

    // ---- s1: weight converts + C GEMM ----
    f2h_kernel<<<(n4_big / 2 + 255) / 256, 256, 0, s1>>>(W_B, WBh, n4_big);
    cudaEventRecord(evWB, s1);
    f2h_kernel<<<(n4_big / 2 + 255) / 256, 256, 0, s1>>>(W_C, WCh, n4_big);
    cudaStreamWaitEvent(s1, evU, 0);
    gemm_mma_h<<<dim3(NOUT_BC / 128, M_TOT / 128), 128, GEMM_SMEM, s1>>>(
        Uh, WCh, b_C, nullptr, C_buf, NOUT_BC, 1);
    cudaEventRecord(evC, s1);

    // ---- s0: Wdt convert, dt GEMM, B GEMM ----
    f2h_kernel<<<(D_SZ * K_DIM / 8 + 255) / 256, 256>>>(W_dt, Wdth,
                                                        D_SZ * K_DIM / 4);
    gemm_mma_h<<<dim3(D_SZ / 128, M_TOT / 128), 128, GEMM_SMEM>>>(
        Uh, Wdth, b_dt, dt_bias, dt_buf, D_SZ, 0);
    cudaStreamWaitEvent(0, evWB, 0);
    gemm_mma_h<<<dim3(NOUT_BC / 128, M_TOT / 128), 128, GEMM_SMEM>>>(
        Uh, WBh, b_B, nullptr, B_buf, NOUT_BC, 1);

    // ---- s0: scan (chain folded into pass2 prologue) ----
    dim3 sgrid(B_SZ * D_SZ / 16, NC);
    scan_pass1<<<sgrid, 256>>>(u, log_A, dt_buf, B_buf, P, H);
    cudaStreamWaitEvent(0, evC, 0);
    scan_pass2<<<sgrid, 256>>>(u, log_A, D_skip, dt_buf, B_buf, C_buf, P, H,
                               out);
}